// round 8
// baseline (speedup 1.0000x reference)
#include <cuda_runtime.h>
#include <cuda_bf16.h>
#include <cstdint>

// ---------------- problem constants ----------------
#define NN   50000
#define NE   800000
#define EDIM 96
#define NDIM 512
#define KIN  608
#define KPAD 640
#define HID  1024
#define OUTD 512

// ---------------- scratch (__device__ globals; no allocation) ----------------
__device__ float          g_agg [(size_t)NN*EDIM];
__device__ __nv_bfloat16  g_xhi [(size_t)NN*KPAD];
__device__ __nv_bfloat16  g_xlo [(size_t)NN*KPAD];
__device__ __nv_bfloat16  g_h1hi[(size_t)NN*HID];
__device__ __nv_bfloat16  g_h1lo[(size_t)NN*HID];
__device__ __nv_bfloat16  g_h2hi[(size_t)NN*HID];
__device__ __nv_bfloat16  g_h2lo[(size_t)NN*HID];
__device__ float          g_y   [(size_t)NN*OUTD];
__device__ __nv_bfloat16  g_w1hi[HID*KPAD];
__device__ __nv_bfloat16  g_w1lo[HID*KPAD];
__device__ __nv_bfloat16  g_w2hi[HID*HID];
__device__ __nv_bfloat16  g_w2lo[HID*HID];
__device__ __nv_bfloat16  g_w3hi[OUTD*HID];
__device__ __nv_bfloat16  g_w3lo[OUTD*HID];

// ---------------- PTX helpers (all sm_80-level, compute_103-safe) ----------------
__device__ __forceinline__ uint32_t smem_u32(const void* p) {
    uint32_t a;
    asm("{ .reg .u64 t; cvta.to.shared.u64 t, %1; cvt.u32.u64 %0, t; }" : "=r"(a) : "l"(p));
    return a;
}

__device__ __forceinline__ void cpasync16(uint32_t saddr, const void* g, bool pred) {
    int sz = pred ? 16 : 0;
    asm volatile("cp.async.cg.shared.global [%0], [%1], 16, %2;"
                 :: "r"(saddr), "l"(g), "r"(sz) : "memory");
}
#define CP_COMMIT() asm volatile("cp.async.commit_group;" ::: "memory")
#define CP_WAIT(n)  asm volatile("cp.async.wait_group %0;" :: "n"(n) : "memory")

__device__ __forceinline__ void ldsm_x4(uint32_t* r, uint32_t saddr) {
    asm volatile("ldmatrix.sync.aligned.m8n8.x4.shared.b16 {%0,%1,%2,%3}, [%4];"
                 : "=r"(r[0]), "=r"(r[1]), "=r"(r[2]), "=r"(r[3]) : "r"(saddr));
}

__device__ __forceinline__ void mma16816(float* d, const uint32_t* a, uint32_t b0, uint32_t b1) {
    asm volatile("mma.sync.aligned.m16n8k16.row.col.f32.bf16.bf16.f32 "
                 "{%0,%1,%2,%3}, {%4,%5,%6,%7}, {%8,%9}, {%0,%1,%2,%3};"
                 : "+f"(d[0]), "+f"(d[1]), "+f"(d[2]), "+f"(d[3])
                 : "r"(a[0]), "r"(a[1]), "r"(a[2]), "r"(a[3]), "r"(b0), "r"(b1));
}

#define SWZ(b) ((b) ^ (((b) >> 3) & 0x70))

// ---------------- aux kernels ----------------
__global__ void zero_agg_kernel() {
    int i = blockIdx.x * blockDim.x + threadIdx.x;
    if (i < NN * EDIM / 4) reinterpret_cast<float4*>(g_agg)[i] = make_float4(0.f, 0.f, 0.f, 0.f);
}

__global__ void scatter_kernel(const float* __restrict__ ef, const int* __restrict__ ei) {
    long idx = (long)blockIdx.x * blockDim.x + threadIdx.x;
    if (idx >= (long)NE * (EDIM / 4)) return;
    int e = (int)(idx / (EDIM / 4));
    int s = (int)(idx % (EDIM / 4));
    int dst = ei[NE + e];  // edge_index row 1 = destinations
    float4 v = *reinterpret_cast<const float4*>(ef + (size_t)e * EDIM + s * 4);
    float* p = g_agg + (size_t)dst * EDIM + s * 4;
    asm volatile("red.global.add.v4.f32 [%0], {%1, %2, %3, %4};"
                 :: "l"(p), "f"(v.x), "f"(v.y), "f"(v.z), "f"(v.w) : "memory");
}

__device__ __forceinline__ void split_store(float v, __nv_bfloat16* hi, __nv_bfloat16* lo, size_t i) {
    __nv_bfloat16 h = __float2bfloat16(v);
    hi[i] = h;
    lo[i] = __float2bfloat16(v - __bfloat162float(h));
}

__global__ void pack_x_kernel(const float* __restrict__ nf) {
    int idx = blockIdx.x * blockDim.x + threadIdx.x;
    if (idx >= NN * KPAD) return;
    int n = idx / KPAD, c = idx - n * KPAD;
    float v;
    if (c < NDIM)      v = nf[(size_t)n * NDIM + c];
    else if (c < KIN)  v = g_agg[(size_t)n * EDIM + (c - NDIM)];
    else               v = 0.f;
    split_store(v, g_xhi, g_xlo, idx);
}

// All three weight matrices: W [K,N] fp32 -> Wt [N,Kpad] bf16 hi/lo in ONE launch
// (transpose + split + zero-pad K). Fused to cut launches and align ncu -s 5 on GEMM2.
#define W1_ELEMS (HID * KPAD)
#define W2_ELEMS (HID * HID)
#define W3_ELEMS (OUTD * HID)
__global__ void conv_wt_all_kernel(const float* __restrict__ W1, const float* __restrict__ W2,
                                   const float* __restrict__ W3) {
    int idx = blockIdx.x * blockDim.x + threadIdx.x;
    const float* W; __nv_bfloat16 *hi, *lo; int K, Kpad, N;
    if (idx < W1_ELEMS) {
        W = W1; hi = g_w1hi; lo = g_w1lo; K = KIN; Kpad = KPAD; N = HID;
    } else if (idx < W1_ELEMS + W2_ELEMS) {
        idx -= W1_ELEMS;
        W = W2; hi = g_w2hi; lo = g_w2lo; K = HID; Kpad = HID; N = HID;
    } else if (idx < W1_ELEMS + W2_ELEMS + W3_ELEMS) {
        idx -= W1_ELEMS + W2_ELEMS;
        W = W3; hi = g_w3hi; lo = g_w3lo; K = HID; Kpad = HID; N = OUTD;
    } else return;
    int n = idx / Kpad, k = idx - n * Kpad;
    float v = (k < K) ? W[(size_t)k * N + n] : 0.f;
    __nv_bfloat16 h = __float2bfloat16(v);
    hi[idx] = h;
    lo[idx] = __float2bfloat16(v - __bfloat162float(h));
}

__global__ void ln_kernel(const float* __restrict__ y, const float* __restrict__ gamma,
                          const float* __restrict__ beta, float* __restrict__ out) {
    int w = (blockIdx.x * blockDim.x + threadIdx.x) >> 5;
    int lane = threadIdx.x & 31;
    if (w >= NN) return;
    const float* row = y + (size_t)w * OUTD;
    float vals[16], s = 0.f, s2 = 0.f;
#pragma unroll
    for (int i = 0; i < 16; i++) {
        float v = row[lane + 32 * i];
        vals[i] = v; s += v; s2 += v * v;
    }
#pragma unroll
    for (int o = 16; o; o >>= 1) {
        s  += __shfl_xor_sync(0xffffffffu, s,  o);
        s2 += __shfl_xor_sync(0xffffffffu, s2, o);
    }
    float mu = s * (1.f / OUTD);
    float var = s2 * (1.f / OUTD) - mu * mu;
    float rstd = rsqrtf(var + 1e-5f);
    float* orow = out + (size_t)w * OUTD;
#pragma unroll
    for (int i = 0; i < 16; i++) {
        int c = lane + 32 * i;
        orow[c] = (vals[i] - mu) * rstd * gamma[c] + beta[c];
    }
}

// ---------------- split-bf16 mma.sync GEMM ----------------
// C[M,N] = act(A @ Bt^T + bias); A (hi/lo) [M,K] bf16 row-major, Bt (hi/lo) [N,K] bf16 row-major.
// CTA tile 128x256, 512 threads (16 warps: 4M x 4N, warp tile 32x64).
// K-chunk 64, SW128 SMEM, cp.async double buffer. 3 split terms: AhBh + AhBl + AlBh.
#define STAGE_BYTES 98304          // Ah,Al 16KB each; Bh,Bl 32KB each
#define A_LO_OFF    16384
#define B_HI_OFF    32768
#define B_LO_OFF    65536
#define GEMM_SMEM   (2 * STAGE_BYTES + 1024)

__global__ void __launch_bounds__(512, 1) gemm_split_kernel(
    const __nv_bfloat16* __restrict__ Ahi, const __nv_bfloat16* __restrict__ Alo,
    const __nv_bfloat16* __restrict__ Bhi, const __nv_bfloat16* __restrict__ Blo,
    const float* __restrict__ bias,
    __nv_bfloat16* __restrict__ Chi, __nv_bfloat16* __restrict__ Clo, float* __restrict__ Cf,
    int M, int K, int N, int NC, int relu) {
    extern __shared__ char smraw[];
    const uint32_t sb = (smem_u32(smraw) + 1023u) & ~1023u;
    const int tid  = threadIdx.x;
    const int wid  = tid >> 5;
    const int lane = tid & 31;
    const int wm = wid & 3;      // 4 warps along M
    const int wn = wid >> 2;     // 4 warps along N
    const int m0  = blockIdx.y * 128;
    const int n0c = blockIdx.x * 256;

    float acc[2][8][4];
#pragma unroll
    for (int a = 0; a < 2; a++)
#pragma unroll
        for (int b = 0; b < 8; b++)
#pragma unroll
            for (int c = 0; c < 4; c++) acc[a][b][c] = 0.f;

    // --- cp.async chunk issue: A 128x64 (hi/lo), B 256x64 (hi/lo), all SW128 ---
    auto issue = [&](int kc) {
        uint32_t st = sb + (uint32_t)(kc & 1) * STAGE_BYTES;
        int k0 = kc * 64;
        // A: 1024 16B-slots -> 2 iters of 512 threads
#pragma unroll
        for (int i = 0; i < 2; i++) {
            int slot = tid + i * 512;
            int row = slot >> 3, ch = slot & 7;
            uint32_t sw = SWZ((uint32_t)(row * 128 + ch * 16));
            int m = m0 + row;
            bool pv = (m < M);
            size_t aoff = (size_t)(pv ? m : 0) * K + k0 + ch * 8;
            cpasync16(st + sw,            Ahi + aoff, pv);
            cpasync16(st + A_LO_OFF + sw, Alo + aoff, pv);
        }
        // B: 2048 16B-slots -> 4 iters of 512 threads
#pragma unroll
        for (int i = 0; i < 4; i++) {
            int slot = tid + i * 512;
            int row = slot >> 3, ch = slot & 7;
            uint32_t sw = SWZ((uint32_t)(row * 128 + ch * 16));
            size_t boff = (size_t)(n0c + row) * K + k0 + ch * 8;
            cpasync16(st + B_HI_OFF + sw, Bhi + boff, true);
            cpasync16(st + B_LO_OFF + sw, Blo + boff, true);
        }
        CP_COMMIT();
    };

    issue(0);
    if (NC > 1) issue(1);

    const int lr = lane & 15, lc = lane >> 4;

    for (int kc = 0; kc < NC; kc++) {
        if (kc + 1 < NC) { CP_WAIT(1); } else { CP_WAIT(0); }
        __syncthreads();

        uint32_t st = sb + (uint32_t)(kc & 1) * STAGE_BYTES;
#pragma unroll
        for (int ks = 0; ks < 4; ks++) {
            uint32_t ah[2][4], al[2][4];
#pragma unroll
            for (int mt = 0; mt < 2; mt++) {
                uint32_t off = SWZ((uint32_t)((wm * 32 + mt * 16 + lr) * 128 + (ks * 2 + lc) * 16));
                ldsm_x4(ah[mt], st + off);
                ldsm_x4(al[mt], st + A_LO_OFF + off);
            }
#pragma unroll
            for (int np = 0; np < 4; np++) {
                uint32_t off = SWZ((uint32_t)((wn * 64 + np * 16 + lr) * 128 + (ks * 2 + lc) * 16));
                uint32_t bh[4], bl[4];
                ldsm_x4(bh, st + B_HI_OFF + off);
                ldsm_x4(bl, st + B_LO_OFF + off);
#pragma unroll
                for (int mt = 0; mt < 2; mt++) {
                    mma16816(acc[mt][np * 2],     ah[mt], bh[0], bh[2]);
                    mma16816(acc[mt][np * 2 + 1], ah[mt], bh[1], bh[3]);
                    mma16816(acc[mt][np * 2],     ah[mt], bl[0], bl[2]);
                    mma16816(acc[mt][np * 2 + 1], ah[mt], bl[1], bl[3]);
                    mma16816(acc[mt][np * 2],     al[mt], bh[0], bh[2]);
                    mma16816(acc[mt][np * 2 + 1], al[mt], bh[1], bh[3]);
                }
            }
        }
        __syncthreads();
        if (kc + 2 < NC) issue(kc + 2);
    }

    // --- epilogue: bias (+ReLU+split-bf16) or fp32 store ---
    const int rbase = m0 + wm * 32 + (lane >> 2);
    const int cq = (lane & 3) * 2;
#pragma unroll
    for (int mt = 0; mt < 2; mt++) {
#pragma unroll
        for (int half = 0; half < 2; half++) {     // d0,d1 vs d2,d3 (row +8)
            int r = rbase + mt * 16 + half * 8;
            if (r >= M) continue;
#pragma unroll
            for (int nt = 0; nt < 8; nt++) {
                int col = n0c + wn * 64 + nt * 8 + cq;
                float v0 = acc[mt][nt][half * 2]     + __ldg(bias + col);
                float v1 = acc[mt][nt][half * 2 + 1] + __ldg(bias + col + 1);
                if (relu) {
                    v0 = fmaxf(v0, 0.f); v1 = fmaxf(v1, 0.f);
                    __nv_bfloat16 h0 = __float2bfloat16(v0), h1 = __float2bfloat16(v1);
                    __nv_bfloat162 ph, pl;
                    ph.x = h0; ph.y = h1;
                    pl.x = __float2bfloat16(v0 - __bfloat162float(h0));
                    pl.y = __float2bfloat16(v1 - __bfloat162float(h1));
                    size_t o = (size_t)r * N + col;
                    *reinterpret_cast<__nv_bfloat162*>(Chi + o) = ph;
                    *reinterpret_cast<__nv_bfloat162*>(Clo + o) = pl;
                } else {
                    float2 v; v.x = v0; v.y = v1;
                    *reinterpret_cast<float2*>(Cf + (size_t)r * N + col) = v;
                }
            }
        }
    }
}

// ---------------- host ----------------
extern "C" void kernel_launch(void* const* d_in, const int* in_sizes, int n_in,
                              void* d_out, int out_size) {
    const float* node_feat = (const float*)d_in[0];
    const float* edge_feat = (const float*)d_in[1];
    const int*   edge_idx  = (const int*)d_in[2];
    // d_in[3] = n_nodes scalar
    const float* W1 = (const float*)d_in[4];
    const float* b1 = (const float*)d_in[5];
    const float* W2 = (const float*)d_in[6];
    const float* b2 = (const float*)d_in[7];
    const float* W3 = (const float*)d_in[8];
    const float* b3 = (const float*)d_in[9];
    const float* gamma = (const float*)d_in[10];
    const float* beta  = (const float*)d_in[11];

    void *p_xhi, *p_xlo, *p_h1hi, *p_h1lo, *p_h2hi, *p_h2lo, *p_y;
    void *p_w1hi, *p_w1lo, *p_w2hi, *p_w2lo, *p_w3hi, *p_w3lo;
    cudaGetSymbolAddress(&p_xhi,  g_xhi);  cudaGetSymbolAddress(&p_xlo,  g_xlo);
    cudaGetSymbolAddress(&p_h1hi, g_h1hi); cudaGetSymbolAddress(&p_h1lo, g_h1lo);
    cudaGetSymbolAddress(&p_h2hi, g_h2hi); cudaGetSymbolAddress(&p_h2lo, g_h2lo);
    cudaGetSymbolAddress(&p_y,    g_y);
    cudaGetSymbolAddress(&p_w1hi, g_w1hi); cudaGetSymbolAddress(&p_w1lo, g_w1lo);
    cudaGetSymbolAddress(&p_w2hi, g_w2hi); cudaGetSymbolAddress(&p_w2lo, g_w2lo);
    cudaGetSymbolAddress(&p_w3hi, g_w3hi); cudaGetSymbolAddress(&p_w3lo, g_w3lo);

    cudaFuncSetAttribute(gemm_split_kernel, cudaFuncAttributeMaxDynamicSharedMemorySize, GEMM_SMEM);

    // launch order matters for ncu (-s 5 -c 1 captures launch #5 = GEMM2):
    // 0:zero 1:scatter 2:pack 3:conv_all 4:gemm1 5:gemm2 6:gemm3 7:ln

    // 1) aggregation
    zero_agg_kernel<<<(NN * EDIM / 4 + 255) / 256, 256>>>();
    scatter_kernel<<<(int)(((long)NE * (EDIM / 4) + 255) / 256), 256>>>(edge_feat, edge_idx);

    // 2) pack inputs + weights (transpose + bf16 hi/lo split)
    pack_x_kernel<<<(NN * KPAD + 255) / 256, 256>>>(node_feat);
    conv_wt_all_kernel<<<(W1_ELEMS + W2_ELEMS + W3_ELEMS + 255) / 256, 256>>>(W1, W2, W3);

    const int mt = (NN + 127) / 128;  // 391

    // 3) MLP (split-bf16 mma.sync GEMMs), CTA tile 128x256
    gemm_split_kernel<<<dim3(HID / 256, mt), 512, GEMM_SMEM>>>(
        (const __nv_bfloat16*)p_xhi, (const __nv_bfloat16*)p_xlo,
        (const __nv_bfloat16*)p_w1hi, (const __nv_bfloat16*)p_w1lo, b1,
        (__nv_bfloat16*)p_h1hi, (__nv_bfloat16*)p_h1lo, nullptr,
        NN, KPAD, HID, KPAD / 64, 1);

    gemm_split_kernel<<<dim3(HID / 256, mt), 512, GEMM_SMEM>>>(
        (const __nv_bfloat16*)p_h1hi, (const __nv_bfloat16*)p_h1lo,
        (const __nv_bfloat16*)p_w2hi, (const __nv_bfloat16*)p_w2lo, b2,
        (__nv_bfloat16*)p_h2hi, (__nv_bfloat16*)p_h2lo, nullptr,
        NN, HID, HID, HID / 64, 1);

    gemm_split_kernel<<<dim3(OUTD / 256, mt), 512, GEMM_SMEM>>>(
        (const __nv_bfloat16*)p_h2hi, (const __nv_bfloat16*)p_h2lo,
        (const __nv_bfloat16*)p_w3hi, (const __nv_bfloat16*)p_w3lo, b3,
        nullptr, nullptr, (float*)p_y,
        NN, HID, OUTD, HID / 64, 0);

    // 4) LayerNorm -> d_out
    ln_kernel<<<(NN + 7) / 8, 256>>>((const float*)p_y, gamma, beta, (float*)d_out);
}

// round 9
// speedup vs baseline: 1.0287x; 1.0287x over previous
#include <cuda_runtime.h>
#include <cuda_bf16.h>
#include <cstdint>

// ---------------- problem constants ----------------
#define NN   50000
#define NE   800000
#define EDIM 96
#define NDIM 512
#define KIN  608
#define KPAD 640
#define HID  1024
#define OUTD 512

// ---------------- scratch (__device__ globals; no allocation) ----------------
__device__ float          g_agg [(size_t)NN*EDIM];
__device__ __nv_bfloat16  g_xhi [(size_t)NN*KPAD];
__device__ __nv_bfloat16  g_xlo [(size_t)NN*KPAD];
__device__ __nv_bfloat16  g_h1hi[(size_t)NN*HID];
__device__ __nv_bfloat16  g_h1lo[(size_t)NN*HID];
__device__ __nv_bfloat16  g_h2hi[(size_t)NN*HID];
__device__ __nv_bfloat16  g_h2lo[(size_t)NN*HID];
__device__ float          g_y   [(size_t)NN*OUTD];
__device__ __nv_bfloat16  g_w1hi[HID*KPAD];
__device__ __nv_bfloat16  g_w1lo[HID*KPAD];
__device__ __nv_bfloat16  g_w2hi[HID*HID];
__device__ __nv_bfloat16  g_w2lo[HID*HID];
__device__ __nv_bfloat16  g_w3hi[OUTD*HID];
__device__ __nv_bfloat16  g_w3lo[OUTD*HID];

// ---------------- PTX helpers (all sm_80-level, compute_103-safe) ----------------
__device__ __forceinline__ uint32_t smem_u32(const void* p) {
    uint32_t a;
    asm("{ .reg .u64 t; cvta.to.shared.u64 t, %1; cvt.u32.u64 %0, t; }" : "=r"(a) : "l"(p));
    return a;
}

__device__ __forceinline__ void cpasync16(uint32_t saddr, const void* g, bool pred) {
    int sz = pred ? 16 : 0;
    asm volatile("cp.async.cg.shared.global [%0], [%1], 16, %2;"
                 :: "r"(saddr), "l"(g), "r"(sz) : "memory");
}
#define CP_COMMIT() asm volatile("cp.async.commit_group;" ::: "memory")
#define CP_WAIT(n)  asm volatile("cp.async.wait_group %0;" :: "n"(n) : "memory")

__device__ __forceinline__ void ldsm_x4(uint32_t* r, uint32_t saddr) {
    asm volatile("ldmatrix.sync.aligned.m8n8.x4.shared.b16 {%0,%1,%2,%3}, [%4];"
                 : "=r"(r[0]), "=r"(r[1]), "=r"(r[2]), "=r"(r[3]) : "r"(saddr));
}

__device__ __forceinline__ void mma16816(float* d, const uint32_t* a, uint32_t b0, uint32_t b1) {
    asm volatile("mma.sync.aligned.m16n8k16.row.col.f32.bf16.bf16.f32 "
                 "{%0,%1,%2,%3}, {%4,%5,%6,%7}, {%8,%9}, {%0,%1,%2,%3};"
                 : "+f"(d[0]), "+f"(d[1]), "+f"(d[2]), "+f"(d[3])
                 : "r"(a[0]), "r"(a[1]), "r"(a[2]), "r"(a[3]), "r"(b0), "r"(b1));
}

#define SWZ(b) ((b) ^ (((b) >> 3) & 0x70))

// ---------------- aux kernels ----------------
__global__ void zero_agg_kernel() {
    int i = blockIdx.x * blockDim.x + threadIdx.x;
    if (i < NN * EDIM / 4) reinterpret_cast<float4*>(g_agg)[i] = make_float4(0.f, 0.f, 0.f, 0.f);
}

__global__ void scatter_kernel(const float* __restrict__ ef, const int* __restrict__ ei) {
    long idx = (long)blockIdx.x * blockDim.x + threadIdx.x;
    if (idx >= (long)NE * (EDIM / 4)) return;
    int e = (int)(idx / (EDIM / 4));
    int s = (int)(idx % (EDIM / 4));
    int dst = ei[NE + e];  // edge_index row 1 = destinations
    float4 v = *reinterpret_cast<const float4*>(ef + (size_t)e * EDIM + s * 4);
    float* p = g_agg + (size_t)dst * EDIM + s * 4;
    asm volatile("red.global.add.v4.f32 [%0], {%1, %2, %3, %4};"
                 :: "l"(p), "f"(v.x), "f"(v.y), "f"(v.z), "f"(v.w) : "memory");
}

__device__ __forceinline__ void split_store(float v, __nv_bfloat16* hi, __nv_bfloat16* lo, size_t i) {
    __nv_bfloat16 h = __float2bfloat16(v);
    hi[i] = h;
    lo[i] = __float2bfloat16(v - __bfloat162float(h));
}

__global__ void pack_x_kernel(const float* __restrict__ nf) {
    int idx = blockIdx.x * blockDim.x + threadIdx.x;
    if (idx >= NN * KPAD) return;
    int n = idx / KPAD, c = idx - n * KPAD;
    float v;
    if (c < NDIM)      v = nf[(size_t)n * NDIM + c];
    else if (c < KIN)  v = g_agg[(size_t)n * EDIM + (c - NDIM)];
    else               v = 0.f;
    split_store(v, g_xhi, g_xlo, idx);
}

// All three weight matrices: W [K,N] fp32 -> Wt [N,Kpad] bf16 hi/lo in ONE launch
#define W1_ELEMS (HID * KPAD)
#define W2_ELEMS (HID * HID)
#define W3_ELEMS (OUTD * HID)
__global__ void conv_wt_all_kernel(const float* __restrict__ W1, const float* __restrict__ W2,
                                   const float* __restrict__ W3) {
    int idx = blockIdx.x * blockDim.x + threadIdx.x;
    const float* W; __nv_bfloat16 *hi, *lo; int K, Kpad, N;
    if (idx < W1_ELEMS) {
        W = W1; hi = g_w1hi; lo = g_w1lo; K = KIN; Kpad = KPAD; N = HID;
    } else if (idx < W1_ELEMS + W2_ELEMS) {
        idx -= W1_ELEMS;
        W = W2; hi = g_w2hi; lo = g_w2lo; K = HID; Kpad = HID; N = HID;
    } else if (idx < W1_ELEMS + W2_ELEMS + W3_ELEMS) {
        idx -= W1_ELEMS + W2_ELEMS;
        W = W3; hi = g_w3hi; lo = g_w3lo; K = HID; Kpad = HID; N = OUTD;
    } else return;
    int n = idx / Kpad, k = idx - n * Kpad;
    float v = (k < K) ? W[(size_t)k * N + n] : 0.f;
    __nv_bfloat16 h = __float2bfloat16(v);
    hi[idx] = h;
    lo[idx] = __float2bfloat16(v - __bfloat162float(h));
}

__global__ void ln_kernel(const float* __restrict__ y, const float* __restrict__ gamma,
                          const float* __restrict__ beta, float* __restrict__ out) {
    int w = (blockIdx.x * blockDim.x + threadIdx.x) >> 5;
    int lane = threadIdx.x & 31;
    if (w >= NN) return;
    const float* row = y + (size_t)w * OUTD;
    float vals[16], s = 0.f, s2 = 0.f;
#pragma unroll
    for (int i = 0; i < 16; i++) {
        float v = row[lane + 32 * i];
        vals[i] = v; s += v; s2 += v * v;
    }
#pragma unroll
    for (int o = 16; o; o >>= 1) {
        s  += __shfl_xor_sync(0xffffffffu, s,  o);
        s2 += __shfl_xor_sync(0xffffffffu, s2, o);
    }
    float mu = s * (1.f / OUTD);
    float var = s2 * (1.f / OUTD) - mu * mu;
    float rstd = rsqrtf(var + 1e-5f);
    float* orow = out + (size_t)w * OUTD;
#pragma unroll
    for (int i = 0; i < 16; i++) {
        int c = lane + 32 * i;
        orow[c] = (vals[i] - mu) * rstd * gamma[c] + beta[c];
    }
}

// ---------------- split-bf16 mma.sync GEMM (term-major MMA order) ----------------
// C[M,N] = act(A @ Bt^T + bias); A (hi/lo) [M,K] bf16 row-major, Bt (hi/lo) [N,K] bf16 row-major.
// CTA tile 128x128, 256 threads (8 warps: 4M x 2N, warp tile 32x64), K-chunk 64,
// SW128 SMEM, cp.async double buffer.
// 3 split terms issued TERM-MAJOR: all AhBh (16 MMAs), then AhBl, then AlBh —
// dependent writes to the same accumulator are 16 instructions apart (was 2).
#define STAGE_BYTES 65536          // Ah,Al,Bh,Bl each 16KB
#define A_LO_OFF    16384
#define B_HI_OFF    32768
#define B_LO_OFF    49152
#define GEMM_SMEM   (2 * STAGE_BYTES + 1024)

__global__ void __launch_bounds__(256, 1) gemm_split_kernel(
    const __nv_bfloat16* __restrict__ Ahi, const __nv_bfloat16* __restrict__ Alo,
    const __nv_bfloat16* __restrict__ Bhi, const __nv_bfloat16* __restrict__ Blo,
    const float* __restrict__ bias,
    __nv_bfloat16* __restrict__ Chi, __nv_bfloat16* __restrict__ Clo, float* __restrict__ Cf,
    int M, int K, int N, int NC, int relu) {
    extern __shared__ char smraw[];
    const uint32_t sb = (smem_u32(smraw) + 1023u) & ~1023u;
    const int tid  = threadIdx.x;
    const int wid  = tid >> 5;
    const int lane = tid & 31;
    const int wm = wid & 3;      // 4 warps along M
    const int wn = wid >> 2;     // 2 warps along N
    const int m0  = blockIdx.y * 128;
    const int n0c = blockIdx.x * 128;

    float acc[2][8][4];
#pragma unroll
    for (int a = 0; a < 2; a++)
#pragma unroll
        for (int b = 0; b < 8; b++)
#pragma unroll
            for (int c = 0; c < 4; c++) acc[a][b][c] = 0.f;

    // --- cp.async chunk issue ---
    auto issue = [&](int kc) {
        uint32_t st = sb + (uint32_t)(kc & 1) * STAGE_BYTES;
        int k0 = kc * 64;
#pragma unroll
        for (int i = 0; i < 4; i++) {
            int slot = tid + i * 256;
            int row = slot >> 3, ch = slot & 7;
            uint32_t sw = SWZ((uint32_t)(row * 128 + ch * 16));
            int m = m0 + row;
            bool pv = (m < M);
            size_t aoff = (size_t)(pv ? m : 0) * K + k0 + ch * 8;
            cpasync16(st + sw,            Ahi + aoff, pv);
            cpasync16(st + A_LO_OFF + sw, Alo + aoff, pv);
            size_t boff = (size_t)(n0c + row) * K + k0 + ch * 8;
            cpasync16(st + B_HI_OFF + sw, Bhi + boff, true);
            cpasync16(st + B_LO_OFF + sw, Blo + boff, true);
        }
        CP_COMMIT();
    };

    issue(0);
    if (NC > 1) issue(1);

    const int lr = lane & 15, lc = lane >> 4;

    for (int kc = 0; kc < NC; kc++) {
        if (kc + 1 < NC) { CP_WAIT(1); } else { CP_WAIT(0); }
        __syncthreads();

        uint32_t st = sb + (uint32_t)(kc & 1) * STAGE_BYTES;
#pragma unroll
        for (int ks = 0; ks < 4; ks++) {
            // Load ALL fragments for this ks first (frees the MMA stream of LDSM deps)
            uint32_t ah[2][4], al[2][4], bh[4][4], bl[4][4];
#pragma unroll
            for (int mt = 0; mt < 2; mt++) {
                uint32_t off = SWZ((uint32_t)((wm * 32 + mt * 16 + lr) * 128 + (ks * 2 + lc) * 16));
                ldsm_x4(ah[mt], st + off);
                ldsm_x4(al[mt], st + A_LO_OFF + off);
            }
#pragma unroll
            for (int np = 0; np < 4; np++) {
                uint32_t off = SWZ((uint32_t)((wn * 64 + np * 16 + lr) * 128 + (ks * 2 + lc) * 16));
                ldsm_x4(bh[np], st + B_HI_OFF + off);
                ldsm_x4(bl[np], st + B_LO_OFF + off);
            }
            // Term-major issue: 16 independent MMAs per term; same-acc RAW spacing = 16.
#pragma unroll
            for (int np = 0; np < 4; np++)
#pragma unroll
                for (int mt = 0; mt < 2; mt++) {
                    mma16816(acc[mt][np * 2],     ah[mt], bh[np][0], bh[np][2]);
                    mma16816(acc[mt][np * 2 + 1], ah[mt], bh[np][1], bh[np][3]);
                }
#pragma unroll
            for (int np = 0; np < 4; np++)
#pragma unroll
                for (int mt = 0; mt < 2; mt++) {
                    mma16816(acc[mt][np * 2],     ah[mt], bl[np][0], bl[np][2]);
                    mma16816(acc[mt][np * 2 + 1], ah[mt], bl[np][1], bl[np][3]);
                }
#pragma unroll
            for (int np = 0; np < 4; np++)
#pragma unroll
                for (int mt = 0; mt < 2; mt++) {
                    mma16816(acc[mt][np * 2],     al[mt], bh[np][0], bh[np][2]);
                    mma16816(acc[mt][np * 2 + 1], al[mt], bh[np][1], bh[np][3]);
                }
        }
        __syncthreads();
        if (kc + 2 < NC) issue(kc + 2);
    }

    // --- epilogue: bias (+ReLU+split-bf16) or fp32 store ---
    const int rbase = m0 + wm * 32 + (lane >> 2);
    const int cq = (lane & 3) * 2;
#pragma unroll
    for (int mt = 0; mt < 2; mt++) {
#pragma unroll
        for (int half = 0; half < 2; half++) {     // d0,d1 vs d2,d3 (row +8)
            int r = rbase + mt * 16 + half * 8;
            if (r >= M) continue;
#pragma unroll
            for (int nt = 0; nt < 8; nt++) {
                int col = n0c + wn * 64 + nt * 8 + cq;
                float v0 = acc[mt][nt][half * 2]     + __ldg(bias + col);
                float v1 = acc[mt][nt][half * 2 + 1] + __ldg(bias + col + 1);
                if (relu) {
                    v0 = fmaxf(v0, 0.f); v1 = fmaxf(v1, 0.f);
                    __nv_bfloat16 h0 = __float2bfloat16(v0), h1 = __float2bfloat16(v1);
                    __nv_bfloat162 ph, pl;
                    ph.x = h0; ph.y = h1;
                    pl.x = __float2bfloat16(v0 - __bfloat162float(h0));
                    pl.y = __float2bfloat16(v1 - __bfloat162float(h1));
                    size_t o = (size_t)r * N + col;
                    *reinterpret_cast<__nv_bfloat162*>(Chi + o) = ph;
                    *reinterpret_cast<__nv_bfloat162*>(Clo + o) = pl;
                } else {
                    float2 v; v.x = v0; v.y = v1;
                    *reinterpret_cast<float2*>(Cf + (size_t)r * N + col) = v;
                }
            }
        }
    }
}

// ---------------- host ----------------
extern "C" void kernel_launch(void* const* d_in, const int* in_sizes, int n_in,
                              void* d_out, int out_size) {
    const float* node_feat = (const float*)d_in[0];
    const float* edge_feat = (const float*)d_in[1];
    const int*   edge_idx  = (const int*)d_in[2];
    // d_in[3] = n_nodes scalar
    const float* W1 = (const float*)d_in[4];
    const float* b1 = (const float*)d_in[5];
    const float* W2 = (const float*)d_in[6];
    const float* b2 = (const float*)d_in[7];
    const float* W3 = (const float*)d_in[8];
    const float* b3 = (const float*)d_in[9];
    const float* gamma = (const float*)d_in[10];
    const float* beta  = (const float*)d_in[11];

    void *p_xhi, *p_xlo, *p_h1hi, *p_h1lo, *p_h2hi, *p_h2lo, *p_y;
    void *p_w1hi, *p_w1lo, *p_w2hi, *p_w2lo, *p_w3hi, *p_w3lo;
    cudaGetSymbolAddress(&p_xhi,  g_xhi);  cudaGetSymbolAddress(&p_xlo,  g_xlo);
    cudaGetSymbolAddress(&p_h1hi, g_h1hi); cudaGetSymbolAddress(&p_h1lo, g_h1lo);
    cudaGetSymbolAddress(&p_h2hi, g_h2hi); cudaGetSymbolAddress(&p_h2lo, g_h2lo);
    cudaGetSymbolAddress(&p_y,    g_y);
    cudaGetSymbolAddress(&p_w1hi, g_w1hi); cudaGetSymbolAddress(&p_w1lo, g_w1lo);
    cudaGetSymbolAddress(&p_w2hi, g_w2hi); cudaGetSymbolAddress(&p_w2lo, g_w2lo);
    cudaGetSymbolAddress(&p_w3hi, g_w3hi); cudaGetSymbolAddress(&p_w3lo, g_w3lo);

    cudaFuncSetAttribute(gemm_split_kernel, cudaFuncAttributeMaxDynamicSharedMemorySize, GEMM_SMEM);

    // 1) aggregation
    zero_agg_kernel<<<(NN * EDIM / 4 + 255) / 256, 256>>>();
    scatter_kernel<<<(int)(((long)NE * (EDIM / 4) + 255) / 256), 256>>>(edge_feat, edge_idx);

    // 2) pack inputs + weights (transpose + bf16 hi/lo split)
    pack_x_kernel<<<(NN * KPAD + 255) / 256, 256>>>(node_feat);
    conv_wt_all_kernel<<<(W1_ELEMS + W2_ELEMS + W3_ELEMS + 255) / 256, 256>>>(W1, W2, W3);

    const int mt = (NN + 127) / 128;  // 391

    // 3) MLP (split-bf16 mma.sync GEMMs), CTA tile 128x128
    gemm_split_kernel<<<dim3(HID / 128, mt), 256, GEMM_SMEM>>>(
        (const __nv_bfloat16*)p_xhi, (const __nv_bfloat16*)p_xlo,
        (const __nv_bfloat16*)p_w1hi, (const __nv_bfloat16*)p_w1lo, b1,
        (__nv_bfloat16*)p_h1hi, (__nv_bfloat16*)p_h1lo, nullptr,
        NN, KPAD, HID, KPAD / 64, 1);

    gemm_split_kernel<<<dim3(HID / 128, mt), 256, GEMM_SMEM>>>(
        (const __nv_bfloat16*)p_h1hi, (const __nv_bfloat16*)p_h1lo,
        (const __nv_bfloat16*)p_w2hi, (const __nv_bfloat16*)p_w2lo, b2,
        (__nv_bfloat16*)p_h2hi, (__nv_bfloat16*)p_h2lo, nullptr,
        NN, HID, HID, HID / 64, 1);

    gemm_split_kernel<<<dim3(OUTD / 128, mt), 256, GEMM_SMEM>>>(
        (const __nv_bfloat16*)p_h2hi, (const __nv_bfloat16*)p_h2lo,
        (const __nv_bfloat16*)p_w3hi, (const __nv_bfloat16*)p_w3lo, b3,
        nullptr, nullptr, (float*)p_y,
        NN, HID, OUTD, HID / 64, 0);

    // 4) LayerNorm -> d_out
    ln_kernel<<<(NN + 7) / 8, 256>>>((const float*)p_y, gamma, beta, (float*)d_out);
}

// round 13
// speedup vs baseline: 1.3583x; 1.3203x over previous
#include <cuda_runtime.h>
#include <cuda_fp16.h>
#include <cstdint>

// ---------------- problem constants ----------------
#define NN   50000
#define NE   800000
#define EDIM 96
#define NDIM 512
#define KIN  608
#define KPAD 640
#define HID  1024
#define OUTD 512

// ---------------- scratch (__device__ globals; no allocation) ----------------
__device__ float   g_agg [(size_t)NN*EDIM];
__device__ __half  g_xhi [(size_t)NN*KPAD];
__device__ __half  g_xlo [(size_t)NN*KPAD];
__device__ __half  g_h1hi[(size_t)NN*HID];
__device__ __half  g_h1lo[(size_t)NN*HID];
__device__ __half  g_h2hi[(size_t)NN*HID];
__device__ __half  g_h2lo[(size_t)NN*HID];
__device__ float   g_y   [(size_t)NN*OUTD];
__device__ __half  g_w1  [HID*KPAD];
__device__ __half  g_w2  [HID*HID];
__device__ __half  g_w3  [OUTD*HID];

// ---------------- PTX helpers (all sm_80-level, compute_103-safe) ----------------
__device__ __forceinline__ uint32_t smem_u32(const void* p) {
    uint32_t a;
    asm("{ .reg .u64 t; cvta.to.shared.u64 t, %1; cvt.u32.u64 %0, t; }" : "=r"(a) : "l"(p));
    return a;
}

__device__ __forceinline__ void cpasync16(uint32_t saddr, const void* g, bool pred) {
    int sz = pred ? 16 : 0;
    asm volatile("cp.async.cg.shared.global [%0], [%1], 16, %2;"
                 :: "r"(saddr), "l"(g), "r"(sz) : "memory");
}
#define CP_COMMIT() asm volatile("cp.async.commit_group;" ::: "memory")
#define CP_WAIT(n)  asm volatile("cp.async.wait_group %0;" :: "n"(n) : "memory")

__device__ __forceinline__ void ldsm_x4(uint32_t* r, uint32_t saddr) {
    asm volatile("ldmatrix.sync.aligned.m8n8.x4.shared.b16 {%0,%1,%2,%3}, [%4];"
                 : "=r"(r[0]), "=r"(r[1]), "=r"(r[2]), "=r"(r[3]) : "r"(saddr));
}

// fp16 inputs, fp32 accumulate
__device__ __forceinline__ void mma16816(float* d, const uint32_t* a, uint32_t b0, uint32_t b1) {
    asm volatile("mma.sync.aligned.m16n8k16.row.col.f32.f16.f16.f32 "
                 "{%0,%1,%2,%3}, {%4,%5,%6,%7}, {%8,%9}, {%0,%1,%2,%3};"
                 : "+f"(d[0]), "+f"(d[1]), "+f"(d[2]), "+f"(d[3])
                 : "r"(a[0]), "r"(a[1]), "r"(a[2]), "r"(a[3]), "r"(b0), "r"(b1));
}

#define SWZ(b) ((b) ^ (((b) >> 3) & 0x70))

// ---------------- aux kernels ----------------
__global__ void zero_agg_kernel() {
    int i = blockIdx.x * blockDim.x + threadIdx.x;
    if (i < NN * EDIM / 4) reinterpret_cast<float4*>(g_agg)[i] = make_float4(0.f, 0.f, 0.f, 0.f);
}

__global__ void scatter_kernel(const float* __restrict__ ef, const int* __restrict__ ei) {
    long idx = (long)blockIdx.x * blockDim.x + threadIdx.x;
    if (idx >= (long)NE * (EDIM / 4)) return;
    int e = (int)(idx / (EDIM / 4));
    int s = (int)(idx % (EDIM / 4));
    int dst = ei[NE + e];  // edge_index row 1 = destinations
    float4 v = *reinterpret_cast<const float4*>(ef + (size_t)e * EDIM + s * 4);
    float* p = g_agg + (size_t)dst * EDIM + s * 4;
    asm volatile("red.global.add.v4.f32 [%0], {%1, %2, %3, %4};"
                 :: "l"(p), "f"(v.x), "f"(v.y), "f"(v.z), "f"(v.w) : "memory");
}

__device__ __forceinline__ void split_store_h(float v, __half* hi, __half* lo, size_t i) {
    __half h = __float2half(v);
    hi[i] = h;
    lo[i] = __float2half(v - __half2float(h));
}

__global__ void pack_x_kernel(const float* __restrict__ nf) {
    int idx = blockIdx.x * blockDim.x + threadIdx.x;
    if (idx >= NN * KPAD) return;
    int n = idx / KPAD, c = idx - n * KPAD;
    float v;
    if (c < NDIM)      v = nf[(size_t)n * NDIM + c];
    else if (c < KIN)  v = g_agg[(size_t)n * EDIM + (c - NDIM)];
    else               v = 0.f;
    split_store_h(v, g_xhi, g_xlo, idx);
}

// All three weight matrices: W [K,N] fp32 -> Wt [N,Kpad] single fp16 in ONE launch
#define W1_ELEMS (HID * KPAD)
#define W2_ELEMS (HID * HID)
#define W3_ELEMS (OUTD * HID)
__global__ void conv_wt_all_kernel(const float* __restrict__ W1, const float* __restrict__ W2,
                                   const float* __restrict__ W3) {
    int idx = blockIdx.x * blockDim.x + threadIdx.x;
    const float* W; __half* wt; int K, Kpad, N;
    if (idx < W1_ELEMS) {
        W = W1; wt = g_w1; K = KIN; Kpad = KPAD; N = HID;
    } else if (idx < W1_ELEMS + W2_ELEMS) {
        idx -= W1_ELEMS;
        W = W2; wt = g_w2; K = HID; Kpad = HID; N = HID;
    } else if (idx < W1_ELEMS + W2_ELEMS + W3_ELEMS) {
        idx -= W1_ELEMS + W2_ELEMS;
        W = W3; wt = g_w3; K = HID; Kpad = HID; N = OUTD;
    } else return;
    int n = idx / Kpad, k = idx - n * Kpad;
    float v = (k < K) ? W[(size_t)k * N + n] : 0.f;
    wt[idx] = __float2half(v);
}

__global__ void ln_kernel(const float* __restrict__ y, const float* __restrict__ gamma,
                          const float* __restrict__ beta, float* __restrict__ out) {
    int w = (blockIdx.x * blockDim.x + threadIdx.x) >> 5;
    int lane = threadIdx.x & 31;
    if (w >= NN) return;
    const float* row = y + (size_t)w * OUTD;
    float vals[16], s = 0.f, s2 = 0.f;
#pragma unroll
    for (int i = 0; i < 16; i++) {
        float v = row[lane + 32 * i];
        vals[i] = v; s += v; s2 += v * v;
    }
#pragma unroll
    for (int o = 16; o; o >>= 1) {
        s  += __shfl_xor_sync(0xffffffffu, s,  o);
        s2 += __shfl_xor_sync(0xffffffffu, s2, o);
    }
    float mu = s * (1.f / OUTD);
    float var = s2 * (1.f / OUTD) - mu * mu;
    float rstd = rsqrtf(var + 1e-5f);
    float* orow = out + (size_t)w * OUTD;
#pragma unroll
    for (int i = 0; i < 16; i++) {
        int c = lane + 32 * i;
        orow[c] = (vals[i] - mu) * rstd * gamma[c] + beta[c];
    }
}

// ---------------- split-fp16 mma.sync GEMM (2 terms) ----------------
// C[M,N] = act((Ahi+Alo) @ Bt^T + bias); Ahi/Alo [M,K] fp16 row-major (hi/lo split of
// fp32 activations, exact to ~2^-22), Bt [N,K] single fp16 row-major.
// Error source = weight rounding only (~1.7e-4 RMS/layer).
// CTA tile 128x128, 256 threads (8 warps: 4M x 2N), K-chunk 64, SW128 SMEM,
// cp.async double buffer. 2 terms: AhB + AlB (32 MMAs/ks vs 48 in the bf16 3-term).
#define STAGE_BYTES 49152          // Ah, Al, B each 16KB
#define A_LO_OFF    16384
#define B_OFF       32768
#define GEMM_SMEM   (2 * STAGE_BYTES + 1024)

__global__ void __launch_bounds__(256, 1) gemm_split_kernel(
    const __half* __restrict__ Ahi, const __half* __restrict__ Alo,
    const __half* __restrict__ B,
    const float* __restrict__ bias,
    __half* __restrict__ Chi, __half* __restrict__ Clo, float* __restrict__ Cf,
    int M, int K, int N, int NC, int relu) {
    extern __shared__ char smraw[];
    const uint32_t sb = (smem_u32(smraw) + 1023u) & ~1023u;
    const int tid  = threadIdx.x;
    const int wid  = tid >> 5;
    const int lane = tid & 31;
    const int wm = wid & 3;      // 4 warps along M
    const int wn = wid >> 2;     // 2 warps along N
    const int m0  = blockIdx.y * 128;
    const int n0c = blockIdx.x * 128;

    float acc[2][8][4];
#pragma unroll
    for (int a = 0; a < 2; a++)
#pragma unroll
        for (int b = 0; b < 8; b++)
#pragma unroll
            for (int c = 0; c < 4; c++) acc[a][b][c] = 0.f;

    // --- cp.async chunk issue: Ah/Al/B each 128x64 fp16 = 1024 16B-slots ---
    auto issue = [&](int kc) {
        uint32_t st = sb + (uint32_t)(kc & 1) * STAGE_BYTES;
        int k0 = kc * 64;
#pragma unroll
        for (int i = 0; i < 4; i++) {
            int slot = tid + i * 256;
            int row = slot >> 3, ch = slot & 7;
            uint32_t sw = SWZ((uint32_t)(row * 128 + ch * 16));
            int m = m0 + row;
            bool pv = (m < M);
            size_t aoff = (size_t)(pv ? m : 0) * K + k0 + ch * 8;
            cpasync16(st + sw,            Ahi + aoff, pv);
            cpasync16(st + A_LO_OFF + sw, Alo + aoff, pv);
            size_t boff = (size_t)(n0c + row) * K + k0 + ch * 8;
            cpasync16(st + B_OFF + sw,    B + boff, true);
        }
        CP_COMMIT();
    };

    issue(0);
    if (NC > 1) issue(1);

    const int lr = lane & 15, lc = lane >> 4;

    for (int kc = 0; kc < NC; kc++) {
        if (kc + 1 < NC) { CP_WAIT(1); } else { CP_WAIT(0); }
        __syncthreads();

        uint32_t st = sb + (uint32_t)(kc & 1) * STAGE_BYTES;
#pragma unroll
        for (int ks = 0; ks < 4; ks++) {
            uint32_t ah[2][4], al[2][4], bf[4][4];
#pragma unroll
            for (int mt = 0; mt < 2; mt++) {
                uint32_t off = SWZ((uint32_t)((wm * 32 + mt * 16 + lr) * 128 + (ks * 2 + lc) * 16));
                ldsm_x4(ah[mt], st + off);
                ldsm_x4(al[mt], st + A_LO_OFF + off);
            }
#pragma unroll
            for (int np = 0; np < 4; np++) {
                uint32_t off = SWZ((uint32_t)((wn * 64 + np * 16 + lr) * 128 + (ks * 2 + lc) * 16));
                ldsm_x4(bf[np], st + B_OFF + off);
            }
            // Term-major: 16 independent MMAs per term
#pragma unroll
            for (int np = 0; np < 4; np++)
#pragma unroll
                for (int mt = 0; mt < 2; mt++) {
                    mma16816(acc[mt][np * 2],     ah[mt], bf[np][0], bf[np][2]);
                    mma16816(acc[mt][np * 2 + 1], ah[mt], bf[np][1], bf[np][3]);
                }
#pragma unroll
            for (int np = 0; np < 4; np++)
#pragma unroll
                for (int mt = 0; mt < 2; mt++) {
                    mma16816(acc[mt][np * 2],     al[mt], bf[np][0], bf[np][2]);
                    mma16816(acc[mt][np * 2 + 1], al[mt], bf[np][1], bf[np][3]);
                }
        }
        __syncthreads();
        if (kc + 2 < NC) issue(kc + 2);
    }

    // --- epilogue: bias (+ReLU+split-fp16) or fp32 store ---
    const int rbase = m0 + wm * 32 + (lane >> 2);
    const int cq = (lane & 3) * 2;
#pragma unroll
    for (int mt = 0; mt < 2; mt++) {
#pragma unroll
        for (int half = 0; half < 2; half++) {     // d0,d1 vs d2,d3 (row +8)
            int r = rbase + mt * 16 + half * 8;
            if (r >= M) continue;
#pragma unroll
            for (int nt = 0; nt < 8; nt++) {
                int col = n0c + wn * 64 + nt * 8 + cq;
                float v0 = acc[mt][nt][half * 2]     + __ldg(bias + col);
                float v1 = acc[mt][nt][half * 2 + 1] + __ldg(bias + col + 1);
                if (relu) {
                    v0 = fmaxf(v0, 0.f); v1 = fmaxf(v1, 0.f);
                    __half h0 = __float2half(v0), h1 = __float2half(v1);
                    __half2 ph, pl;
                    ph.x = h0; ph.y = h1;
                    pl.x = __float2half(v0 - __half2float(h0));
                    pl.y = __float2half(v1 - __half2float(h1));
                    size_t o = (size_t)r * N + col;
                    *reinterpret_cast<__half2*>(Chi + o) = ph;
                    *reinterpret_cast<__half2*>(Clo + o) = pl;
                } else {
                    float2 v; v.x = v0; v.y = v1;
                    *reinterpret_cast<float2*>(Cf + (size_t)r * N + col) = v;
                }
            }
        }
    }
}

// ---------------- host ----------------
extern "C" void kernel_launch(void* const* d_in, const int* in_sizes, int n_in,
                              void* d_out, int out_size) {
    const float* node_feat = (const float*)d_in[0];
    const float* edge_feat = (const float*)d_in[1];
    const int*   edge_idx  = (const int*)d_in[2];
    // d_in[3] = n_nodes scalar
    const float* W1 = (const float*)d_in[4];
    const float* b1 = (const float*)d_in[5];
    const float* W2 = (const float*)d_in[6];
    const float* b2 = (const float*)d_in[7];
    const float* W3 = (const float*)d_in[8];
    const float* b3 = (const float*)d_in[9];
    const float* gamma = (const float*)d_in[10];
    const float* beta  = (const float*)d_in[11];

    void *p_xhi, *p_xlo, *p_h1hi, *p_h1lo, *p_h2hi, *p_h2lo, *p_y;
    void *p_w1, *p_w2, *p_w3;
    cudaGetSymbolAddress(&p_xhi,  g_xhi);  cudaGetSymbolAddress(&p_xlo,  g_xlo);
    cudaGetSymbolAddress(&p_h1hi, g_h1hi); cudaGetSymbolAddress(&p_h1lo, g_h1lo);
    cudaGetSymbolAddress(&p_h2hi, g_h2hi); cudaGetSymbolAddress(&p_h2lo, g_h2lo);
    cudaGetSymbolAddress(&p_y,    g_y);
    cudaGetSymbolAddress(&p_w1,   g_w1);
    cudaGetSymbolAddress(&p_w2,   g_w2);
    cudaGetSymbolAddress(&p_w3,   g_w3);

    cudaFuncSetAttribute(gemm_split_kernel, cudaFuncAttributeMaxDynamicSharedMemorySize, GEMM_SMEM);

    // 1) aggregation
    zero_agg_kernel<<<(NN * EDIM / 4 + 255) / 256, 256>>>();
    scatter_kernel<<<(int)(((long)NE * (EDIM / 4) + 255) / 256), 256>>>(edge_feat, edge_idx);

    // 2) pack inputs (fp16 hi/lo) + weights (single fp16)
    pack_x_kernel<<<(NN * KPAD + 255) / 256, 256>>>(node_feat);
    conv_wt_all_kernel<<<(W1_ELEMS + W2_ELEMS + W3_ELEMS + 255) / 256, 256>>>(W1, W2, W3);

    const int mt = (NN + 127) / 128;  // 391

    // 3) MLP (2-term split-fp16 mma.sync GEMMs), CTA tile 128x128
    gemm_split_kernel<<<dim3(HID / 128, mt), 256, GEMM_SMEM>>>(
        (const __half*)p_xhi, (const __half*)p_xlo, (const __half*)p_w1, b1,
        (__half*)p_h1hi, (__half*)p_h1lo, nullptr,
        NN, KPAD, HID, KPAD / 64, 1);

    gemm_split_kernel<<<dim3(HID / 128, mt), 256, GEMM_SMEM>>>(
        (const __half*)p_h1hi, (const __half*)p_h1lo, (const __half*)p_w2, b2,
        (__half*)p_h2hi, (__half*)p_h2lo, nullptr,
        NN, HID, HID, HID / 64, 1);

    gemm_split_kernel<<<dim3(OUTD / 128, mt), 256, GEMM_SMEM>>>(
        (const __half*)p_h2hi, (const __half*)p_h2lo, (const __half*)p_w3, b3,
        nullptr, nullptr, (float*)p_y,
        NN, HID, OUTD, HID / 64, 0);

    // 4) LayerNorm -> d_out
    ln_kernel<<<(NN + 7) / 8, 256>>>((const float*)p_y, gamma, beta, (float*)d_out);
}

// round 14
// speedup vs baseline: 2.2329x; 1.6439x over previous
#include <cuda_runtime.h>
#include <cuda_fp16.h>
#include <cstdint>

// ---------------- problem constants ----------------
#define NN   50000
#define NE   800000
#define EDIM 96
#define NDIM 512
#define KIN  608
#define KPAD 640
#define HID  1024
#define OUTD 512

// ---------------- scratch (__device__ globals; no allocation) ----------------
__device__ float   g_agg[(size_t)NN*EDIM];
__device__ __half  g_x  [(size_t)NN*KPAD];
__device__ __half  g_h1 [(size_t)NN*HID];
__device__ __half  g_h2 [(size_t)NN*HID];
__device__ float   g_y  [(size_t)NN*OUTD];
__device__ __half  g_w1 [HID*KPAD];
__device__ __half  g_w2 [HID*HID];
__device__ __half  g_w3 [OUTD*HID];

// ---------------- PTX helpers (all sm_80-level, compute_103-safe) ----------------
__device__ __forceinline__ uint32_t smem_u32(const void* p) {
    uint32_t a;
    asm("{ .reg .u64 t; cvta.to.shared.u64 t, %1; cvt.u32.u64 %0, t; }" : "=r"(a) : "l"(p));
    return a;
}

__device__ __forceinline__ void cpasync16(uint32_t saddr, const void* g, bool pred) {
    int sz = pred ? 16 : 0;
    asm volatile("cp.async.cg.shared.global [%0], [%1], 16, %2;"
                 :: "r"(saddr), "l"(g), "r"(sz) : "memory");
}
#define CP_COMMIT() asm volatile("cp.async.commit_group;" ::: "memory")
#define CP_WAIT(n)  asm volatile("cp.async.wait_group %0;" :: "n"(n) : "memory")

__device__ __forceinline__ void ldsm_x4(uint32_t* r, uint32_t saddr) {
    asm volatile("ldmatrix.sync.aligned.m8n8.x4.shared.b16 {%0,%1,%2,%3}, [%4];"
                 : "=r"(r[0]), "=r"(r[1]), "=r"(r[2]), "=r"(r[3]) : "r"(saddr));
}

// fp16 inputs, fp32 accumulate
__device__ __forceinline__ void mma16816(float* d, const uint32_t* a, uint32_t b0, uint32_t b1) {
    asm volatile("mma.sync.aligned.m16n8k16.row.col.f32.f16.f16.f32 "
                 "{%0,%1,%2,%3}, {%4,%5,%6,%7}, {%8,%9}, {%0,%1,%2,%3};"
                 : "+f"(d[0]), "+f"(d[1]), "+f"(d[2]), "+f"(d[3])
                 : "r"(a[0]), "r"(a[1]), "r"(a[2]), "r"(a[3]), "r"(b0), "r"(b1));
}

#define SWZ(b) ((b) ^ (((b) >> 3) & 0x70))

// ---------------- aux kernels ----------------
__global__ void zero_agg_kernel() {
    int i = blockIdx.x * blockDim.x + threadIdx.x;
    if (i < NN * EDIM / 4) reinterpret_cast<float4*>(g_agg)[i] = make_float4(0.f, 0.f, 0.f, 0.f);
}

__global__ void scatter_kernel(const float* __restrict__ ef, const int* __restrict__ ei) {
    long idx = (long)blockIdx.x * blockDim.x + threadIdx.x;
    if (idx >= (long)NE * (EDIM / 4)) return;
    int e = (int)(idx / (EDIM / 4));
    int s = (int)(idx % (EDIM / 4));
    int dst = ei[NE + e];  // edge_index row 1 = destinations
    float4 v = *reinterpret_cast<const float4*>(ef + (size_t)e * EDIM + s * 4);
    float* p = g_agg + (size_t)dst * EDIM + s * 4;
    asm volatile("red.global.add.v4.f32 [%0], {%1, %2, %3, %4};"
                 :: "l"(p), "f"(v.x), "f"(v.y), "f"(v.z), "f"(v.w) : "memory");
}

__global__ void pack_x_kernel(const float* __restrict__ nf) {
    int idx = blockIdx.x * blockDim.x + threadIdx.x;
    if (idx >= NN * KPAD) return;
    int n = idx / KPAD, c = idx - n * KPAD;
    float v;
    if (c < NDIM)      v = nf[(size_t)n * NDIM + c];
    else if (c < KIN)  v = g_agg[(size_t)n * EDIM + (c - NDIM)];
    else               v = 0.f;
    g_x[idx] = __float2half(v);
}

// All three weight matrices: W [K,N] fp32 -> Wt [N,Kpad] single fp16 in ONE launch
#define W1_ELEMS (HID * KPAD)
#define W2_ELEMS (HID * HID)
#define W3_ELEMS (OUTD * HID)
__global__ void conv_wt_all_kernel(const float* __restrict__ W1, const float* __restrict__ W2,
                                   const float* __restrict__ W3) {
    int idx = blockIdx.x * blockDim.x + threadIdx.x;
    const float* W; __half* wt; int K, Kpad, N;
    if (idx < W1_ELEMS) {
        W = W1; wt = g_w1; K = KIN; Kpad = KPAD; N = HID;
    } else if (idx < W1_ELEMS + W2_ELEMS) {
        idx -= W1_ELEMS;
        W = W2; wt = g_w2; K = HID; Kpad = HID; N = HID;
    } else if (idx < W1_ELEMS + W2_ELEMS + W3_ELEMS) {
        idx -= W1_ELEMS + W2_ELEMS;
        W = W3; wt = g_w3; K = HID; Kpad = HID; N = OUTD;
    } else return;
    int n = idx / Kpad, k = idx - n * Kpad;
    float v = (k < K) ? W[(size_t)k * N + n] : 0.f;
    wt[idx] = __float2half(v);
}

__global__ void ln_kernel(const float* __restrict__ y, const float* __restrict__ gamma,
                          const float* __restrict__ beta, float* __restrict__ out) {
    int w = (blockIdx.x * blockDim.x + threadIdx.x) >> 5;
    int lane = threadIdx.x & 31;
    if (w >= NN) return;
    const float* row = y + (size_t)w * OUTD;
    float vals[16], s = 0.f, s2 = 0.f;
#pragma unroll
    for (int i = 0; i < 16; i++) {
        float v = row[lane + 32 * i];
        vals[i] = v; s += v; s2 += v * v;
    }
#pragma unroll
    for (int o = 16; o; o >>= 1) {
        s  += __shfl_xor_sync(0xffffffffu, s,  o);
        s2 += __shfl_xor_sync(0xffffffffu, s2, o);
    }
    float mu = s * (1.f / OUTD);
    float var = s2 * (1.f / OUTD) - mu * mu;
    float rstd = rsqrtf(var + 1e-5f);
    float* orow = out + (size_t)w * OUTD;
#pragma unroll
    for (int i = 0; i < 16; i++) {
        int c = lane + 32 * i;
        orow[c] = (vals[i] - mu) * rstd * gamma[c] + beta[c];
    }
}

// ---------------- single-term fp16 mma.sync GEMM ----------------
// C[M,N] = act(A @ Bt^T + bias); A [M,K] fp16 row-major, Bt [N,K] fp16 row-major.
// Error budget: weight + activation rounding, ~4.8e-4 total after 3 layers (gate 1e-3).
// CTA tile 128x128, 256 threads (8 warps: 4M x 2N, warp tile 32x64), K-chunk 64,
// SW128 SMEM, cp.async double buffer. 16 MMAs/ks.
#define STAGE_BYTES 32768          // A, B each 16KB
#define B_OFF       16384
#define GEMM_SMEM   (2 * STAGE_BYTES + 1024)

__global__ void __launch_bounds__(256, 1) gemm_fp16_kernel(
    const __half* __restrict__ A,
    const __half* __restrict__ B,
    const float* __restrict__ bias,
    __half* __restrict__ Ch, float* __restrict__ Cf,
    int M, int K, int N, int NC, int relu) {
    extern __shared__ char smraw[];
    const uint32_t sb = (smem_u32(smraw) + 1023u) & ~1023u;
    const int tid  = threadIdx.x;
    const int wid  = tid >> 5;
    const int lane = tid & 31;
    const int wm = wid & 3;      // 4 warps along M
    const int wn = wid >> 2;     // 2 warps along N
    const int m0  = blockIdx.y * 128;
    const int n0c = blockIdx.x * 128;

    float acc[2][8][4];
#pragma unroll
    for (int a = 0; a < 2; a++)
#pragma unroll
        for (int b = 0; b < 8; b++)
#pragma unroll
            for (int c = 0; c < 4; c++) acc[a][b][c] = 0.f;

    // --- cp.async chunk issue: A/B each 128x64 fp16 = 1024 16B-slots ---
    auto issue = [&](int kc) {
        uint32_t st = sb + (uint32_t)(kc & 1) * STAGE_BYTES;
        int k0 = kc * 64;
#pragma unroll
        for (int i = 0; i < 4; i++) {
            int slot = tid + i * 256;
            int row = slot >> 3, ch = slot & 7;
            uint32_t sw = SWZ((uint32_t)(row * 128 + ch * 16));
            int m = m0 + row;
            bool pv = (m < M);
            size_t aoff = (size_t)(pv ? m : 0) * K + k0 + ch * 8;
            cpasync16(st + sw,         A + aoff, pv);
            size_t boff = (size_t)(n0c + row) * K + k0 + ch * 8;
            cpasync16(st + B_OFF + sw, B + boff, true);
        }
        CP_COMMIT();
    };

    issue(0);
    if (NC > 1) issue(1);

    const int lr = lane & 15, lc = lane >> 4;

    for (int kc = 0; kc < NC; kc++) {
        if (kc + 1 < NC) { CP_WAIT(1); } else { CP_WAIT(0); }
        __syncthreads();

        uint32_t st = sb + (uint32_t)(kc & 1) * STAGE_BYTES;
#pragma unroll
        for (int ks = 0; ks < 4; ks++) {
            uint32_t af[2][4], bf[4][4];
#pragma unroll
            for (int mt = 0; mt < 2; mt++) {
                uint32_t off = SWZ((uint32_t)((wm * 32 + mt * 16 + lr) * 128 + (ks * 2 + lc) * 16));
                ldsm_x4(af[mt], st + off);
            }
#pragma unroll
            for (int np = 0; np < 4; np++) {
                uint32_t off = SWZ((uint32_t)((wn * 64 + np * 16 + lr) * 128 + (ks * 2 + lc) * 16));
                ldsm_x4(bf[np], st + B_OFF + off);
            }
#pragma unroll
            for (int np = 0; np < 4; np++)
#pragma unroll
                for (int mt = 0; mt < 2; mt++) {
                    mma16816(acc[mt][np * 2],     af[mt], bf[np][0], bf[np][2]);
                    mma16816(acc[mt][np * 2 + 1], af[mt], bf[np][1], bf[np][3]);
                }
        }
        __syncthreads();
        if (kc + 2 < NC) issue(kc + 2);
    }

    // --- epilogue: bias (+ReLU+fp16 store) or fp32 store ---
    const int rbase = m0 + wm * 32 + (lane >> 2);
    const int cq = (lane & 3) * 2;
#pragma unroll
    for (int mt = 0; mt < 2; mt++) {
#pragma unroll
        for (int half = 0; half < 2; half++) {     // d0,d1 vs d2,d3 (row +8)
            int r = rbase + mt * 16 + half * 8;
            if (r >= M) continue;
#pragma unroll
            for (int nt = 0; nt < 8; nt++) {
                int col = n0c + wn * 64 + nt * 8 + cq;
                float v0 = acc[mt][nt][half * 2]     + __ldg(bias + col);
                float v1 = acc[mt][nt][half * 2 + 1] + __ldg(bias + col + 1);
                if (relu) {
                    v0 = fmaxf(v0, 0.f); v1 = fmaxf(v1, 0.f);
                    __half2 ph;
                    ph.x = __float2half(v0); ph.y = __float2half(v1);
                    *reinterpret_cast<__half2*>(Ch + (size_t)r * N + col) = ph;
                } else {
                    float2 v; v.x = v0; v.y = v1;
                    *reinterpret_cast<float2*>(Cf + (size_t)r * N + col) = v;
                }
            }
        }
    }
}

// ---------------- host ----------------
extern "C" void kernel_launch(void* const* d_in, const int* in_sizes, int n_in,
                              void* d_out, int out_size) {
    const float* node_feat = (const float*)d_in[0];
    const float* edge_feat = (const float*)d_in[1];
    const int*   edge_idx  = (const int*)d_in[2];
    // d_in[3] = n_nodes scalar
    const float* W1 = (const float*)d_in[4];
    const float* b1 = (const float*)d_in[5];
    const float* W2 = (const float*)d_in[6];
    const float* b2 = (const float*)d_in[7];
    const float* W3 = (const float*)d_in[8];
    const float* b3 = (const float*)d_in[9];
    const float* gamma = (const float*)d_in[10];
    const float* beta  = (const float*)d_in[11];

    void *p_x, *p_h1, *p_h2, *p_y, *p_w1, *p_w2, *p_w3;
    cudaGetSymbolAddress(&p_x,  g_x);
    cudaGetSymbolAddress(&p_h1, g_h1);
    cudaGetSymbolAddress(&p_h2, g_h2);
    cudaGetSymbolAddress(&p_y,  g_y);
    cudaGetSymbolAddress(&p_w1, g_w1);
    cudaGetSymbolAddress(&p_w2, g_w2);
    cudaGetSymbolAddress(&p_w3, g_w3);

    cudaFuncSetAttribute(gemm_fp16_kernel, cudaFuncAttributeMaxDynamicSharedMemorySize, GEMM_SMEM);

    // 1) aggregation
    zero_agg_kernel<<<(NN * EDIM / 4 + 255) / 256, 256>>>();
    scatter_kernel<<<(int)(((long)NE * (EDIM / 4) + 255) / 256), 256>>>(edge_feat, edge_idx);

    // 2) pack inputs (fp16) + weights (fp16)
    pack_x_kernel<<<(NN * KPAD + 255) / 256, 256>>>(node_feat);
    conv_wt_all_kernel<<<(W1_ELEMS + W2_ELEMS + W3_ELEMS + 255) / 256, 256>>>(W1, W2, W3);

    const int mt = (NN + 127) / 128;  // 391

    // 3) MLP (single-term fp16 mma.sync GEMMs), CTA tile 128x128
    gemm_fp16_kernel<<<dim3(HID / 128, mt), 256, GEMM_SMEM>>>(
        (const __half*)p_x, (const __half*)p_w1, b1,
        (__half*)p_h1, nullptr,
        NN, KPAD, HID, KPAD / 64, 1);

    gemm_fp16_kernel<<<dim3(HID / 128, mt), 256, GEMM_SMEM>>>(
        (const __half*)p_h1, (const __half*)p_w2, b2,
        (__half*)p_h2, nullptr,
        NN, HID, HID, HID / 64, 1);

    gemm_fp16_kernel<<<dim3(OUTD / 128, mt), 256, GEMM_SMEM>>>(
        (const __half*)p_h2, (const __half*)p_w3, b3,
        nullptr, (float*)p_y,
        NN, HID, OUTD, HID / 64, 0);

    // 4) LayerNorm -> d_out
    ln_kernel<<<(NN + 7) / 8, 256>>>((const float*)p_y, gamma, beta, (float*)d_out);
}

// round 15
// speedup vs baseline: 2.5292x; 1.1327x over previous
#include <cuda_runtime.h>
#include <cuda_fp16.h>
#include <cstdint>

// ---------------- problem constants ----------------
#define NN   50000
#define NE   800000
#define EDIM 96
#define NDIM 512
#define KIN  608
#define KPAD 640
#define HID  1024
#define OUTD 512

// ---------------- scratch (__device__ globals; no allocation) ----------------
__device__ float   g_agg[(size_t)NN*EDIM];
__device__ __half  g_x  [(size_t)NN*KPAD];
__device__ __half  g_h1 [(size_t)NN*HID];
__device__ __half  g_h2 [(size_t)NN*HID];
__device__ float   g_y  [(size_t)NN*OUTD];
__device__ __half  g_w1 [HID*KPAD];
__device__ __half  g_w2 [HID*HID];
__device__ __half  g_w3 [OUTD*HID];

// ---------------- PTX helpers (all sm_80-level, compute_103-safe) ----------------
__device__ __forceinline__ uint32_t smem_u32(const void* p) {
    uint32_t a;
    asm("{ .reg .u64 t; cvta.to.shared.u64 t, %1; cvt.u32.u64 %0, t; }" : "=r"(a) : "l"(p));
    return a;
}

__device__ __forceinline__ void cpasync16(uint32_t saddr, const void* g, bool pred) {
    int sz = pred ? 16 : 0;
    asm volatile("cp.async.cg.shared.global [%0], [%1], 16, %2;"
                 :: "r"(saddr), "l"(g), "r"(sz) : "memory");
}
#define CP_COMMIT() asm volatile("cp.async.commit_group;" ::: "memory")
#define CP_WAIT(n)  asm volatile("cp.async.wait_group %0;" :: "n"(n) : "memory")

__device__ __forceinline__ void ldsm_x4(uint32_t* r, uint32_t saddr) {
    asm volatile("ldmatrix.sync.aligned.m8n8.x4.shared.b16 {%0,%1,%2,%3}, [%4];"
                 : "=r"(r[0]), "=r"(r[1]), "=r"(r[2]), "=r"(r[3]) : "r"(saddr));
}

// fp16 inputs, fp32 accumulate
__device__ __forceinline__ void mma16816(float* d, const uint32_t* a, uint32_t b0, uint32_t b1) {
    asm volatile("mma.sync.aligned.m16n8k16.row.col.f32.f16.f16.f32 "
                 "{%0,%1,%2,%3}, {%4,%5,%6,%7}, {%8,%9}, {%0,%1,%2,%3};"
                 : "+f"(d[0]), "+f"(d[1]), "+f"(d[2]), "+f"(d[3])
                 : "r"(a[0]), "r"(a[1]), "r"(a[2]), "r"(a[3]), "r"(b0), "r"(b1));
}

#define SWZ(b) ((b) ^ (((b) >> 3) & 0x70))

// ---------------- aux kernels ----------------
__global__ void zero_agg_kernel() {
    int i = blockIdx.x * blockDim.x + threadIdx.x;
    if (i < NN * EDIM / 4) reinterpret_cast<float4*>(g_agg)[i] = make_float4(0.f, 0.f, 0.f, 0.f);
}

__global__ void scatter_kernel(const float* __restrict__ ef, const int* __restrict__ ei) {
    long idx = (long)blockIdx.x * blockDim.x + threadIdx.x;
    if (idx >= (long)NE * (EDIM / 4)) return;
    int e = (int)(idx / (EDIM / 4));
    int s = (int)(idx % (EDIM / 4));
    int dst = ei[NE + e];  // edge_index row 1 = destinations
    float4 v = *reinterpret_cast<const float4*>(ef + (size_t)e * EDIM + s * 4);
    float* p = g_agg + (size_t)dst * EDIM + s * 4;
    asm volatile("red.global.add.v4.f32 [%0], {%1, %2, %3, %4};"
                 :: "l"(p), "f"(v.x), "f"(v.y), "f"(v.z), "f"(v.w) : "memory");
}

__global__ void pack_x_kernel(const float* __restrict__ nf) {
    int idx = blockIdx.x * blockDim.x + threadIdx.x;
    if (idx >= NN * KPAD) return;
    int n = idx / KPAD, c = idx - n * KPAD;
    float v;
    if (c < NDIM)      v = nf[(size_t)n * NDIM + c];
    else if (c < KIN)  v = g_agg[(size_t)n * EDIM + (c - NDIM)];
    else               v = 0.f;
    g_x[idx] = __float2half(v);
}

// All three weight matrices: W [K,N] fp32 -> Wt [N,Kpad] single fp16 in ONE launch
#define W1_ELEMS (HID * KPAD)
#define W2_ELEMS (HID * HID)
#define W3_ELEMS (OUTD * HID)
__global__ void conv_wt_all_kernel(const float* __restrict__ W1, const float* __restrict__ W2,
                                   const float* __restrict__ W3) {
    int idx = blockIdx.x * blockDim.x + threadIdx.x;
    const float* W; __half* wt; int K, Kpad, N;
    if (idx < W1_ELEMS) {
        W = W1; wt = g_w1; K = KIN; Kpad = KPAD; N = HID;
    } else if (idx < W1_ELEMS + W2_ELEMS) {
        idx -= W1_ELEMS;
        W = W2; wt = g_w2; K = HID; Kpad = HID; N = HID;
    } else if (idx < W1_ELEMS + W2_ELEMS + W3_ELEMS) {
        idx -= W1_ELEMS + W2_ELEMS;
        W = W3; wt = g_w3; K = HID; Kpad = HID; N = OUTD;
    } else return;
    int n = idx / Kpad, k = idx - n * Kpad;
    float v = (k < K) ? W[(size_t)k * N + n] : 0.f;
    wt[idx] = __float2half(v);
}

__global__ void ln_kernel(const float* __restrict__ y, const float* __restrict__ gamma,
                          const float* __restrict__ beta, float* __restrict__ out) {
    int w = (blockIdx.x * blockDim.x + threadIdx.x) >> 5;
    int lane = threadIdx.x & 31;
    if (w >= NN) return;
    const float* row = y + (size_t)w * OUTD;
    float vals[16], s = 0.f, s2 = 0.f;
#pragma unroll
    for (int i = 0; i < 16; i++) {
        float v = row[lane + 32 * i];
        vals[i] = v; s += v; s2 += v * v;
    }
#pragma unroll
    for (int o = 16; o; o >>= 1) {
        s  += __shfl_xor_sync(0xffffffffu, s,  o);
        s2 += __shfl_xor_sync(0xffffffffu, s2, o);
    }
    float mu = s * (1.f / OUTD);
    float var = s2 * (1.f / OUTD) - mu * mu;
    float rstd = rsqrtf(var + 1e-5f);
    float* orow = out + (size_t)w * OUTD;
#pragma unroll
    for (int i = 0; i < 16; i++) {
        int c = lane + 32 * i;
        orow[c] = (vals[i] - mu) * rstd * gamma[c] + beta[c];
    }
}

// ---------------- single-term fp16 mma.sync GEMM, 2 CTAs/SM ----------------
// C[M,N] = act(A @ Bt^T + bias); A [M,K] fp16 row-major, Bt [N,K] fp16 row-major.
// CTA tile 128x128, 256 threads (8 warps: 4M x 2N), K-chunk 64, SW128 SMEM,
// cp.async double buffer. 66.5KB SMEM/CTA -> 2 CTAs/SM co-resident: independent
// CTAs overlap each other's __syncthreads / cp.async-wait windows (same-CTA warps
// cannot, per round-8 measurement).
#define STAGE_BYTES 32768          // A, B each 16KB
#define B_OFF       16384
#define GEMM_SMEM   (2 * STAGE_BYTES + 1024)

__global__ void __launch_bounds__(256, 2) gemm_fp16_kernel(
    const __half* __restrict__ A,
    const __half* __restrict__ B,
    const float* __restrict__ bias,
    __half* __restrict__ Ch, float* __restrict__ Cf,
    int M, int K, int N, int NC, int relu) {
    extern __shared__ char smraw[];
    const uint32_t sb = (smem_u32(smraw) + 1023u) & ~1023u;
    const int tid  = threadIdx.x;
    const int wid  = tid >> 5;
    const int lane = tid & 31;
    const int wm = wid & 3;      // 4 warps along M
    const int wn = wid >> 2;     // 2 warps along N
    const int m0  = blockIdx.y * 128;
    const int n0c = blockIdx.x * 128;

    float acc[2][8][4];
#pragma unroll
    for (int a = 0; a < 2; a++)
#pragma unroll
        for (int b = 0; b < 8; b++)
#pragma unroll
            for (int c = 0; c < 4; c++) acc[a][b][c] = 0.f;

    // --- cp.async chunk issue: A/B each 128x64 fp16 = 1024 16B-slots ---
    auto issue = [&](int kc) {
        uint32_t st = sb + (uint32_t)(kc & 1) * STAGE_BYTES;
        int k0 = kc * 64;
#pragma unroll
        for (int i = 0; i < 4; i++) {
            int slot = tid + i * 256;
            int row = slot >> 3, ch = slot & 7;
            uint32_t sw = SWZ((uint32_t)(row * 128 + ch * 16));
            int m = m0 + row;
            bool pv = (m < M);
            size_t aoff = (size_t)(pv ? m : 0) * K + k0 + ch * 8;
            cpasync16(st + sw,         A + aoff, pv);
            size_t boff = (size_t)(n0c + row) * K + k0 + ch * 8;
            cpasync16(st + B_OFF + sw, B + boff, true);
        }
        CP_COMMIT();
    };

    issue(0);
    if (NC > 1) issue(1);

    const int lr = lane & 15, lc = lane >> 4;

    for (int kc = 0; kc < NC; kc++) {
        if (kc + 1 < NC) { CP_WAIT(1); } else { CP_WAIT(0); }
        __syncthreads();

        uint32_t st = sb + (uint32_t)(kc & 1) * STAGE_BYTES;
#pragma unroll
        for (int ks = 0; ks < 4; ks++) {
            uint32_t af[2][4], bf[4][4];
#pragma unroll
            for (int mt = 0; mt < 2; mt++) {
                uint32_t off = SWZ((uint32_t)((wm * 32 + mt * 16 + lr) * 128 + (ks * 2 + lc) * 16));
                ldsm_x4(af[mt], st + off);
            }
#pragma unroll
            for (int np = 0; np < 4; np++) {
                uint32_t off = SWZ((uint32_t)((wn * 64 + np * 16 + lr) * 128 + (ks * 2 + lc) * 16));
                ldsm_x4(bf[np], st + B_OFF + off);
            }
#pragma unroll
            for (int np = 0; np < 4; np++)
#pragma unroll
                for (int mt = 0; mt < 2; mt++) {
                    mma16816(acc[mt][np * 2],     af[mt], bf[np][0], bf[np][2]);
                    mma16816(acc[mt][np * 2 + 1], af[mt], bf[np][1], bf[np][3]);
                }
        }
        __syncthreads();
        if (kc + 2 < NC) issue(kc + 2);
    }

    // --- epilogue: bias (+ReLU+fp16 store) or fp32 store ---
    const int rbase = m0 + wm * 32 + (lane >> 2);
    const int cq = (lane & 3) * 2;
#pragma unroll
    for (int mt = 0; mt < 2; mt++) {
#pragma unroll
        for (int half = 0; half < 2; half++) {     // d0,d1 vs d2,d3 (row +8)
            int r = rbase + mt * 16 + half * 8;
            if (r >= M) continue;
#pragma unroll
            for (int nt = 0; nt < 8; nt++) {
                int col = n0c + wn * 64 + nt * 8 + cq;
                float v0 = acc[mt][nt][half * 2]     + __ldg(bias + col);
                float v1 = acc[mt][nt][half * 2 + 1] + __ldg(bias + col + 1);
                if (relu) {
                    v0 = fmaxf(v0, 0.f); v1 = fmaxf(v1, 0.f);
                    __half2 ph;
                    ph.x = __float2half(v0); ph.y = __float2half(v1);
                    *reinterpret_cast<__half2*>(Ch + (size_t)r * N + col) = ph;
                } else {
                    float2 v; v.x = v0; v.y = v1;
                    *reinterpret_cast<float2*>(Cf + (size_t)r * N + col) = v;
                }
            }
        }
    }
}

// ---------------- host ----------------
extern "C" void kernel_launch(void* const* d_in, const int* in_sizes, int n_in,
                              void* d_out, int out_size) {
    const float* node_feat = (const float*)d_in[0];
    const float* edge_feat = (const float*)d_in[1];
    const int*   edge_idx  = (const int*)d_in[2];
    // d_in[3] = n_nodes scalar
    const float* W1 = (const float*)d_in[4];
    const float* b1 = (const float*)d_in[5];
    const float* W2 = (const float*)d_in[6];
    const float* b2 = (const float*)d_in[7];
    const float* W3 = (const float*)d_in[8];
    const float* b3 = (const float*)d_in[9];
    const float* gamma = (const float*)d_in[10];
    const float* beta  = (const float*)d_in[11];

    void *p_x, *p_h1, *p_h2, *p_y, *p_w1, *p_w2, *p_w3;
    cudaGetSymbolAddress(&p_x,  g_x);
    cudaGetSymbolAddress(&p_h1, g_h1);
    cudaGetSymbolAddress(&p_h2, g_h2);
    cudaGetSymbolAddress(&p_y,  g_y);
    cudaGetSymbolAddress(&p_w1, g_w1);
    cudaGetSymbolAddress(&p_w2, g_w2);
    cudaGetSymbolAddress(&p_w3, g_w3);

    cudaFuncSetAttribute(gemm_fp16_kernel, cudaFuncAttributeMaxDynamicSharedMemorySize, GEMM_SMEM);

    // 1) aggregation
    zero_agg_kernel<<<(NN * EDIM / 4 + 255) / 256, 256>>>();
    scatter_kernel<<<(int)(((long)NE * (EDIM / 4) + 255) / 256), 256>>>(edge_feat, edge_idx);

    // 2) pack inputs (fp16) + weights (fp16)
    pack_x_kernel<<<(NN * KPAD + 255) / 256, 256>>>(node_feat);
    conv_wt_all_kernel<<<(W1_ELEMS + W2_ELEMS + W3_ELEMS + 255) / 256, 256>>>(W1, W2, W3);

    const int mt = (NN + 127) / 128;  // 391

    // 3) MLP (single-term fp16 mma.sync GEMMs), CTA tile 128x128, 2 CTAs/SM
    gemm_fp16_kernel<<<dim3(HID / 128, mt), 256, GEMM_SMEM>>>(
        (const __half*)p_x, (const __half*)p_w1, b1,
        (__half*)p_h1, nullptr,
        NN, KPAD, HID, KPAD / 64, 1);

    gemm_fp16_kernel<<<dim3(HID / 128, mt), 256, GEMM_SMEM>>>(
        (const __half*)p_h1, (const __half*)p_w2, b2,
        (__half*)p_h2, nullptr,
        NN, HID, HID, HID / 64, 1);

    gemm_fp16_kernel<<<dim3(OUTD / 128, mt), 256, GEMM_SMEM>>>(
        (const __half*)p_h2, (const __half*)p_w3, b3,
        nullptr, (float*)p_y,
        NN, HID, OUTD, HID / 64, 0);

    // 4) LayerNorm -> d_out
    ln_kernel<<<(NN + 7) / 8, 256>>>((const float*)p_y, gamma, beta, (float*)d_out);
}